// round 3
// baseline (speedup 1.0000x reference)
#include <cuda_runtime.h>
#include <cuda_bf16.h>

// Problem constants (fixed by the dataset's reference_code)
#define HW_DIM     512
#define NB         6
#define NLOOPS     4
#define NDET       4096
#define NSAMP      128
#define NBATCH     4
#define NPTS       (NDET * NSAMP)          // 524288
#define PIX        (512 * 512)             // 262144 pixels per channel
#define B_STRIDE   (2 * NB * PIX)          // per-batch elements in input (12 ch)
#define ILP        4                       // independent points per thread

// Repacked refinement: [BATCH][NB][H][W] of float2 (x,y interleaved) = 50.3 MB
__device__ float2 g_packed[NBATCH * NB * PIX];

// ---------------------------------------------------------------------------
// Kernel 1: repack [B,12,H,W] f32 -> [B,6,H,W] float2. Fully coalesced,
// float4 in / float4 out. DRAM-bound (100 MB round trip ~= 12.5 us floor).
// ---------------------------------------------------------------------------
__global__ void __launch_bounds__(256)
repack_kernel(const float* __restrict__ refinement)
{
    // each thread: 4 pixels of one (batch,bucket) slice
    int t = blockIdx.x * blockDim.x + threadIdx.x;
    const int total = NBATCH * NB * (PIX / 4);
    if (t >= total) return;

    const int quad  = t % (PIX / 4);
    const int slice = t / (PIX / 4);        // b*NB + k
    const int p     = quad * 4;

    const int b = slice / NB;
    const int k = slice - b * NB;

    const float* ch0 = refinement + (long)b * B_STRIDE + (long)(2 * k)     * PIX;
    const float* ch1 = refinement + (long)b * B_STRIDE + (long)(2 * k + 1) * PIX;

    const float4 xs = *reinterpret_cast<const float4*>(ch0 + p);
    const float4 ys = *reinterpret_cast<const float4*>(ch1 + p);

    float4* dst = reinterpret_cast<float4*>(&g_packed[(long)slice * PIX + p]);
    dst[0] = make_float4(xs.x, ys.x, xs.y, ys.y);
    dst[1] = make_float4(xs.z, ys.z, xs.w, ys.w);
}

// ---------------------------------------------------------------------------
// Kernel 2: iterative refinement gather, ILP=4 independent points/thread.
// Phase-structured per iteration to maximize loads in flight.
// ---------------------------------------------------------------------------
__global__ void __launch_bounds__(256)
refine_kernel(const float*  __restrict__ det_in,     // [NDET, NSAMP, 2]
              const float*  __restrict__ sampling,   // [NSAMP]
              const int*    __restrict__ bvec,       // [NDET]
              float*        __restrict__ out)        // [NDET, NSAMP, 2]
{
    // Thread handles points t0 + i*256 (i < ILP): consecutive lanes stay
    // coalesced for det/out I/O.
    const int t0 = blockIdx.x * (blockDim.x * ILP) + threadIdx.x;

    float x[ILP], y[ILP], w0[ILP], w1[ILP];
    int   off0[ILP], off1[ILP];   // element offsets into g_packed
    int   prev[ILP];
    bool  done[ILP];

    #pragma unroll
    for (int i = 0; i < ILP; ++i) {
        const int t = t0 + i * 256;
        const int s = t & (NSAMP - 1);
        const int d = t >> 7;

        // Per-sample bucket setup — reference arithmetic exactly.
        const float base = sampling[s] * (float)NB;
        const float bif  = floorf(base);
        const int   bint = (int)bif;

        const float d0 = fabsf(bif - base);
        w0[i] = (d0 > 1.0f) ? 0.0f : (1.0f - d0);
        const float d1 = fabsf((bif + 1.0f) - base);
        w1[i] = (d1 > 1.0f) ? 0.0f : (1.0f - d1);

        const int k0 = bint % NB;
        const int k1 = (bint + 1) % NB;
        const int bb = bvec[d] * NB;
        off0[i] = (bb + k0) * PIX;
        off1[i] = (bb + k1) * PIX;

        const float2 det = reinterpret_cast<const float2*>(det_in)[t];
        x[i] = det.x;  y[i] = det.y;
        prev[i] = -1;  done[i] = false;
    }

    #pragma unroll
    for (int l = 0; l < NLOOPS; ++l) {
        float xr[ILP], yr[ILP];
        int   pix[ILP];
        bool  act[ILP];
        float2 g0[ILP], g1[ILP];

        // Phase A: compute pixels + fixed-point detection
        #pragma unroll
        for (int i = 0; i < ILP; ++i) {
            act[i] = !done[i];
            if (act[i]) {
                float xv = rintf(x[i]);      // round-half-even == jnp.round
                float yv = rintf(y[i]);
                xv = fminf(fmaxf(xv, 0.0f), (float)(HW_DIM - 1));
                yv = fminf(fmaxf(yv, 0.0f), (float)(HW_DIM - 1));
                xr[i] = xv;  yr[i] = yv;
                pix[i] = (int)yv * HW_DIM + (int)xv;
                if (pix[i] == prev[i]) { done[i] = true; act[i] = false; }
                else                   { prev[i] = pix[i]; }
            }
        }

        // Phase B: issue all gathers (independent -> max MLP)
        #pragma unroll
        for (int i = 0; i < ILP; ++i) {
            if (act[i]) {
                g0[i] = __ldg(&g_packed[off0[i] + pix[i]]);
                g1[i] = __ldg(&g_packed[off1[i] + pix[i]]);
            }
        }

        // Phase C: consume
        #pragma unroll
        for (int i = 0; i < ILP; ++i) {
            if (act[i]) {
                x[i] = xr[i] + (w0[i] * g0[i].x + w1[i] * g1[i].x);
                y[i] = yr[i] + (w0[i] * g0[i].y + w1[i] * g1[i].y);
            }
        }
    }

    #pragma unroll
    for (int i = 0; i < ILP; ++i) {
        const int t = t0 + i * 256;
        reinterpret_cast<float2*>(out)[t] = make_float2(x[i], y[i]);
    }
}

extern "C" void kernel_launch(void* const* d_in, const int* in_sizes, int n_in,
                              void* d_out, int out_size)
{
    // Identify inputs by element count:
    //   det_indices : 1048576 f32, refinement : 12582912 f32,
    //   sampling : 128 f32, b : 4096 i32
    const float* det_in     = nullptr;
    const float* refinement = nullptr;
    const float* sampling   = nullptr;
    const int*   bvec       = nullptr;

    for (int i = 0; i < n_in; ++i) {
        switch (in_sizes[i]) {
            case 1048576:  det_in     = (const float*)d_in[i]; break;
            case 12582912: refinement = (const float*)d_in[i]; break;
            case 128:      sampling   = (const float*)d_in[i]; break;
            case 4096:     bvec       = (const int*)d_in[i];   break;
            default: break;
        }
    }

    {
        const int total   = NBATCH * NB * (PIX / 4);
        const int threads = 256;
        const int blocks  = (total + threads - 1) / threads;
        repack_kernel<<<blocks, threads>>>(refinement);
    }
    {
        const int threads = 256;
        const int blocks  = NPTS / (threads * ILP);   // 512, exact
        refine_kernel<<<blocks, threads>>>(det_in, sampling, bvec,
                                           (float*)d_out);
    }
}

// round 4
// speedup vs baseline: 1.2866x; 1.2866x over previous
#include <cuda_runtime.h>
#include <cuda_bf16.h>

// Problem constants (fixed by the dataset's reference_code)
#define HW_DIM     512
#define NB         6
#define NLOOPS     4
#define NDET       4096
#define NSAMP      128
#define NPTS       (NDET * NSAMP)          // 524288
#define PIX        (512 * 512)             // per-channel elements
#define B_STRIDE   (2 * NB * PIX)          // per-batch elements (12 channels)

// ---------------------------------------------------------------------------
// Fused iterative refinement gather, original layout, early exit.
//  * off=-1 tap is provably zero-weight -> 2 taps, 4 scalar gathers/iter.
//  * Fixed point: if the rounded pixel repeats, the response is bit-identical
//    and det is unchanged for all remaining iterations -> skip (exact).
// ---------------------------------------------------------------------------
__global__ void __launch_bounds__(256)
refine_kernel(const float*  __restrict__ det_in,     // [NDET, NSAMP, 2]
              const float*  __restrict__ refinement, // [BATCH, 12, 512, 512]
              const float*  __restrict__ sampling,   // [NSAMP]
              const int*    __restrict__ bvec,       // [NDET]
              float*        __restrict__ out)        // [NDET, NSAMP, 2]
{
    const int t = blockIdx.x * blockDim.x + threadIdx.x;
    if (t >= NPTS) return;

    const int s = t & (NSAMP - 1);
    const int d = t >> 7;

    // Per-sample bucket setup — reproduce reference arithmetic exactly.
    const float base = sampling[s] * (float)NB;
    const float bif  = floorf(base);
    const int   bint = (int)bif;

    const float d0 = fabsf(bif - base);
    const float w0 = (d0 > 1.0f) ? 0.0f : (1.0f - d0);
    const float d1 = fabsf((bif + 1.0f) - base);
    const float w1 = (d1 > 1.0f) ? 0.0f : (1.0f - d1);

    const int c0 = (bint % NB) * 2;          // bint in [0, 5]
    const int c1 = ((bint + 1) % NB) * 2;    // wraps 6 -> 0

    const float* __restrict__ refb = refinement + (long)bvec[d] * B_STRIDE;
    const float* __restrict__ p0x  = refb + (long)c0 * PIX;
    const float* __restrict__ p1x  = refb + (long)c1 * PIX;

    float2 det = reinterpret_cast<const float2*>(det_in)[t];
    float x = det.x, y = det.y;

    int prev_pix = -1;
    #pragma unroll
    for (int l = 0; l < NLOOPS; ++l) {
        float xr = rintf(x);                 // round-half-even == jnp.round
        float yr = rintf(y);
        xr = fminf(fmaxf(xr, 0.0f), (float)(HW_DIM - 1));
        yr = fminf(fmaxf(yr, 0.0f), (float)(HW_DIM - 1));
        const int pix = (int)yr * HW_DIM + (int)xr;

        // Exact fixed-point exit: identical pixel => identical response
        // => det invariant for this and all remaining iterations.
        if (pix == prev_pix) break;
        prev_pix = pix;

        // 4 independent gathers, issued together (L2/DRAM overlap)
        const float r0x = __ldg(p0x + pix);
        const float r0y = __ldg(p0x + PIX + pix);
        const float r1x = __ldg(p1x + pix);
        const float r1y = __ldg(p1x + PIX + pix);

        x = xr + (w0 * r0x + w1 * r1x);
        y = yr + (w0 * r0y + w1 * r1y);
    }

    reinterpret_cast<float2*>(out)[t] = make_float2(x, y);
}

extern "C" void kernel_launch(void* const* d_in, const int* in_sizes, int n_in,
                              void* d_out, int out_size)
{
    // Identify inputs by element count:
    //   det_indices : 1048576 f32, refinement : 12582912 f32,
    //   sampling : 128 f32, b : 4096 i32
    const float* det_in     = nullptr;
    const float* refinement = nullptr;
    const float* sampling   = nullptr;
    const int*   bvec       = nullptr;

    for (int i = 0; i < n_in; ++i) {
        switch (in_sizes[i]) {
            case 1048576:  det_in     = (const float*)d_in[i]; break;
            case 12582912: refinement = (const float*)d_in[i]; break;
            case 128:      sampling   = (const float*)d_in[i]; break;
            case 4096:     bvec       = (const int*)d_in[i];   break;
            default: break;
        }
    }

    const int threads = 256;
    const int blocks  = (NPTS + threads - 1) / threads;
    refine_kernel<<<blocks, threads>>>(det_in, refinement, sampling, bvec,
                                       (float*)d_out);
}

// round 5
// speedup vs baseline: 1.3775x; 1.0707x over previous
#include <cuda_runtime.h>
#include <cuda_bf16.h>

// Problem constants (fixed by the dataset's reference_code)
#define HW_DIM     512
#define NB         6
#define NLOOPS     4
#define NDET       4096
#define NSAMP      128
#define NPTS       (NDET * NSAMP)          // 524288
#define PIX        (512 * 512)             // per-channel elements
#define B_STRIDE   (2 * NB * PIX)          // per-batch elements (12 channels)

// ---------------------------------------------------------------------------
// Fused iterative refinement gather, original layout.
// Exact work-skipping:
//  * off=-1 tap is provably zero-weight -> 2 taps, 4 scalar gathers/iter.
//  * det_{l+1} = G(pix_l): the update is a pure function of the pixel index
//    (rounded+clipped coords are recoverable from pix; weights/channels are
//    per-thread constants). Hence:
//      - pix_l == pix_{l-1}  -> fixed point: det never changes again.
//      - pix_l == pix_{l-2}  -> 2-cycle: trajectory alternates; the final det
//        is the current det if (NLOOPS - l) is even, else the previous det.
//    Both checks are bit-exact; they skip only provably-identical recompute.
// ---------------------------------------------------------------------------
__global__ void __launch_bounds__(256)
refine_kernel(const float*  __restrict__ det_in,     // [NDET, NSAMP, 2]
              const float*  __restrict__ refinement, // [BATCH, 12, 512, 512]
              const float*  __restrict__ sampling,   // [NSAMP]
              const int*    __restrict__ bvec,       // [NDET]
              float*        __restrict__ out)        // [NDET, NSAMP, 2]
{
    const int t = blockIdx.x * blockDim.x + threadIdx.x;  // grid exact

    const int s = t & (NSAMP - 1);
    const int d = t >> 7;

    // Per-sample bucket setup — reproduce reference arithmetic exactly.
    const float base = sampling[s] * (float)NB;
    const float bif  = floorf(base);
    const int   bint = (int)bif;

    const float d0 = fabsf(bif - base);
    const float w0 = (d0 > 1.0f) ? 0.0f : (1.0f - d0);
    const float d1 = fabsf((bif + 1.0f) - base);
    const float w1 = (d1 > 1.0f) ? 0.0f : (1.0f - d1);

    const int c0 = (bint % NB) * 2;          // bint in [0, 5]
    const int c1 = ((bint + 1) % NB) * 2;    // wraps 6 -> 0

    const float* __restrict__ refb = refinement + (long)bvec[d] * B_STRIDE;
    const float* __restrict__ p0x  = refb + (long)c0 * PIX;
    const float* __restrict__ p1x  = refb + (long)c1 * PIX;

    float2 det = reinterpret_cast<const float2*>(det_in)[t];
    float x = det.x, y = det.y;
    float px = x,  py = y;                   // det_{l-1} (valid once prev2 set)

    int prev1 = -1, prev2 = -1;
    #pragma unroll
    for (int l = 0; l < NLOOPS; ++l) {
        float xr = rintf(x);                 // round-half-even == jnp.round
        float yr = rintf(y);
        xr = fminf(fmaxf(xr, 0.0f), (float)(HW_DIM - 1));
        yr = fminf(fmaxf(yr, 0.0f), (float)(HW_DIM - 1));
        const int pix = (int)yr * HW_DIM + (int)xr;

        // Fixed point: det_{l+1} = det_l forever -> output current det.
        if (pix == prev1) break;

        // 2-cycle: det alternates between previous and current forever.
        if (pix == prev2) {
            if ((NLOOPS - l) & 1) { x = px; y = py; }  // odd remaining -> prev
            break;
        }

        prev2 = prev1;  prev1 = pix;
        px = x;  py = y;                     // save det_l before update

        // 4 independent gathers, issued together (L2/DRAM overlap)
        const float r0x = __ldg(p0x + pix);
        const float r0y = __ldg(p0x + PIX + pix);
        const float r1x = __ldg(p1x + pix);
        const float r1y = __ldg(p1x + PIX + pix);

        x = xr + (w0 * r0x + w1 * r1x);
        y = yr + (w0 * r0y + w1 * r1y);
    }

    reinterpret_cast<float2*>(out)[t] = make_float2(x, y);
}

extern "C" void kernel_launch(void* const* d_in, const int* in_sizes, int n_in,
                              void* d_out, int out_size)
{
    // Identify inputs by element count:
    //   det_indices : 1048576 f32, refinement : 12582912 f32,
    //   sampling : 128 f32, b : 4096 i32
    const float* det_in     = nullptr;
    const float* refinement = nullptr;
    const float* sampling   = nullptr;
    const int*   bvec       = nullptr;

    for (int i = 0; i < n_in; ++i) {
        switch (in_sizes[i]) {
            case 1048576:  det_in     = (const float*)d_in[i]; break;
            case 12582912: refinement = (const float*)d_in[i]; break;
            case 128:      sampling   = (const float*)d_in[i]; break;
            case 4096:     bvec       = (const int*)d_in[i];   break;
            default: break;
        }
    }

    const int threads = 256;
    const int blocks  = NPTS / threads;      // 2048, exact
    refine_kernel<<<blocks, threads>>>(det_in, refinement, sampling, bvec,
                                       (float*)d_out);
}